// round 1
// baseline (speedup 1.0000x reference)
#include <cuda_runtime.h>
#include <math.h>

#define BATCH 4
#define CFULL 512
#define HC 256
#define HH 128
#define WW 128
#define HW (HH*WW)

// Scratch (device globals — allocation-free per harness rules)
__device__ float g_x1[BATCH * HC * HW];     // dwconv(a1) result, 64 MiB
__device__ float g_pool[BATCH * HC * 4];    // p2: max-pool of x[:,256:] to 2x2, [b][cc][q]
__device__ float g_base[BATCH * 4 * CFULL]; // per-(batch,quadrant) bias: [b][q][o]

// ---------------------------------------------------------------------------
// Kernel 1: adaptive max pool of channels 256..511 to 2x2
// block = (b, cc, q); 256 threads reduce a 64x64 quadrant
// ---------------------------------------------------------------------------
__global__ __launch_bounds__(256) void pool_kernel(const float* __restrict__ x) {
    int blk = blockIdx.x;
    int q  = blk & 3;
    int cc = (blk >> 2) & 255;
    int b  = blk >> 10;
    int qh = q >> 1, qw = q & 1;
    const float* xin = x + ((size_t)(b * CFULL + 256 + cc)) * HW + qh * 64 * WW + qw * 64;

    float m = -INFINITY;
    for (int i = threadIdx.x; i < 4096; i += 256) {
        int r = i >> 6, col = i & 63;
        m = fmaxf(m, xin[r * WW + col]);
    }
    __shared__ float red[256];
    red[threadIdx.x] = m;
    __syncthreads();
    for (int s = 128; s > 0; s >>= 1) {
        if (threadIdx.x < s) red[threadIdx.x] = fmaxf(red[threadIdx.x], red[threadIdx.x + s]);
        __syncthreads();
    }
    if (threadIdx.x == 0) g_pool[(b * HC + cc) * 4 + q] = red[0];
}

// ---------------------------------------------------------------------------
// Kernel 2: tiny 2x2 dwconvs (levels 2/3/4) + base[b][q][o] =
//           ba[o] + sum_cc wa[o, 256+cc] * catlow[cc][q]
// grid = BATCH, 512 threads
// ---------------------------------------------------------------------------
__global__ __launch_bounds__(512) void base_kernel(
    const float* __restrict__ w2, const float* __restrict__ b2,
    const float* __restrict__ w3, const float* __restrict__ b3,
    const float* __restrict__ w4, const float* __restrict__ b4,
    const float* __restrict__ wa, const float* __restrict__ ba)
{
    int b = blockIdx.x;
    __shared__ float catlow[256][4];
    int t = threadIdx.x;
    if (t < 256) {
        const float* wp;
        float bias;
        if (t < 128)       { wp = w2 + t * 9;        bias = b2[t];        }
        else if (t < 192)  { wp = w3 + (t - 128) * 9; bias = b3[t - 128]; }
        else               { wp = w4 + (t - 192) * 9; bias = b4[t - 192]; }
        float i00 = g_pool[(b * HC + t) * 4 + 0];
        float i01 = g_pool[(b * HC + t) * 4 + 1];
        float i10 = g_pool[(b * HC + t) * 4 + 2];
        float i11 = g_pool[(b * HC + t) * 4 + 3];
        // dwconv3 (pad 1) on the 2x2 map
        catlow[t][0] = i00*wp[4] + i01*wp[5] + i10*wp[7] + i11*wp[8] + bias;
        catlow[t][1] = i00*wp[3] + i01*wp[4] + i10*wp[6] + i11*wp[7] + bias;
        catlow[t][2] = i00*wp[1] + i01*wp[2] + i10*wp[4] + i11*wp[5] + bias;
        catlow[t][3] = i00*wp[0] + i01*wp[1] + i10*wp[3] + i11*wp[4] + bias;
    }
    __syncthreads();
    int o = t;
    float a0 = ba[o], a1 = a0, a2 = a0, a3 = a0;
    #pragma unroll 4
    for (int cc = 0; cc < 256; ++cc) {
        float wv = wa[o * CFULL + 256 + cc];
        a0 = fmaf(wv, catlow[cc][0], a0);
        a1 = fmaf(wv, catlow[cc][1], a1);
        a2 = fmaf(wv, catlow[cc][2], a2);
        a3 = fmaf(wv, catlow[cc][3], a3);
    }
    g_base[(b * 4 + 0) * CFULL + o] = a0;
    g_base[(b * 4 + 1) * CFULL + o] = a1;
    g_base[(b * 4 + 2) * CFULL + o] = a2;
    g_base[(b * 4 + 3) * CFULL + o] = a3;
}

// ---------------------------------------------------------------------------
// Kernel 3: full-res depthwise 3x3 conv on channels 0..255 -> g_x1
// one thread per output element
// ---------------------------------------------------------------------------
__global__ __launch_bounds__(256) void dwconv_kernel(
    const float* __restrict__ x, const float* __restrict__ w1, const float* __restrict__ b1)
{
    int idx = blockIdx.x * 256 + threadIdx.x;
    int wcol = idx & 127;
    int hrow = (idx >> 7) & 127;
    int c = (idx >> 14) & 255;
    int b = idx >> 22;
    const float* xin = x + ((size_t)(b * CFULL + c)) * HW;
    const float* wp = w1 + c * 9;
    float acc = b1[c];
    #pragma unroll
    for (int ky = 0; ky < 3; ky++) {
        int hh = hrow + ky - 1;
        if (hh < 0 || hh > 127) continue;
        #pragma unroll
        for (int kx = 0; kx < 3; kx++) {
            int wc = wcol + kx - 1;
            if (wc < 0 || wc > 127) continue;
            acc = fmaf(wp[ky * 3 + kx], xin[hh * WW + wc], acc);
        }
    }
    g_x1[idx] = acc;
}

// ---------------------------------------------------------------------------
// Kernel 4: fused GEMM + base + exact GELU + gate-by-x
//   out[b,o,p] = gelu( sum_{k<256} wa[o,k]*x1[b,k,p] + base[b,q(p),o] ) * x[b,o,p]
// Tile: 64 (o) x 64 (p), BK=16, 256 threads, 4x4 per thread.
// ---------------------------------------------------------------------------
__device__ __forceinline__ float gelu_exact(float v) {
    return 0.5f * v * (1.0f + erff(v * 0.70710678118654752f));
}

__global__ __launch_bounds__(256) void gemm_gelu_kernel(
    const float* __restrict__ x, const float* __restrict__ wa, float* __restrict__ out)
{
    __shared__ float As[16][65];  // [k][m] (wa tile, transposed, padded)
    __shared__ float Bs[16][64];  // [k][n] (x1 tile)

    int b  = blockIdx.z;
    int po = blockIdx.x * 64;   // pixel offset within batch image (0..16383)
    int oo = blockIdx.y * 64;   // output-channel offset
    int tid = threadIdx.x;
    int tx = tid & 15, ty = tid >> 4;

    const float* x1b = g_x1 + (size_t)b * HC * HW;

    float acc[4][4] = {};

    for (int k0 = 0; k0 < 256; k0 += 16) {
        // Load wa tile: As[k][m] = wa[(oo+m)*512 + k0+k]
        {
            int m  = tid >> 2;
            int kk = (tid & 3) * 4;
            float4 v = *reinterpret_cast<const float4*>(&wa[(oo + m) * CFULL + k0 + kk]);
            As[kk + 0][m] = v.x;
            As[kk + 1][m] = v.y;
            As[kk + 2][m] = v.z;
            As[kk + 3][m] = v.w;
        }
        // Load x1 tile: Bs[k][n] = x1[(k0+k)*HW + po+n]
        {
            int k = tid >> 4;
            int n = (tid & 15) * 4;
            float4 v = *reinterpret_cast<const float4*>(&x1b[(size_t)(k0 + k) * HW + po + n]);
            *reinterpret_cast<float4*>(&Bs[k][n]) = v;
        }
        __syncthreads();
        #pragma unroll
        for (int k = 0; k < 16; ++k) {
            float a0 = As[k][ty * 4 + 0];
            float a1 = As[k][ty * 4 + 1];
            float a2 = As[k][ty * 4 + 2];
            float a3 = As[k][ty * 4 + 3];
            float4 bb = *reinterpret_cast<float4*>(&Bs[k][tx * 4]);
            acc[0][0] = fmaf(a0, bb.x, acc[0][0]);
            acc[0][1] = fmaf(a0, bb.y, acc[0][1]);
            acc[0][2] = fmaf(a0, bb.z, acc[0][2]);
            acc[0][3] = fmaf(a0, bb.w, acc[0][3]);
            acc[1][0] = fmaf(a1, bb.x, acc[1][0]);
            acc[1][1] = fmaf(a1, bb.y, acc[1][1]);
            acc[1][2] = fmaf(a1, bb.z, acc[1][2]);
            acc[1][3] = fmaf(a1, bb.w, acc[1][3]);
            acc[2][0] = fmaf(a2, bb.x, acc[2][0]);
            acc[2][1] = fmaf(a2, bb.y, acc[2][1]);
            acc[2][2] = fmaf(a2, bb.z, acc[2][2]);
            acc[2][3] = fmaf(a2, bb.w, acc[2][3]);
            acc[3][0] = fmaf(a3, bb.x, acc[3][0]);
            acc[3][1] = fmaf(a3, bb.y, acc[3][1]);
            acc[3][2] = fmaf(a3, bb.z, acc[3][2]);
            acc[3][3] = fmaf(a3, bb.w, acc[3][3]);
        }
        __syncthreads();
    }

    // Quadrant is constant per block: 64 consecutive p lie in one row-half.
    int h = po / WW;
    int q = ((h >= 64) ? 2 : 0) + (((po % WW) >= 64) ? 1 : 0);
    const float* basep = g_base + (b * 4 + q) * CFULL + oo;

    #pragma unroll
    for (int i = 0; i < 4; ++i) {
        int o = oo + ty * 4 + i;
        float bs = basep[ty * 4 + i];
        size_t off = ((size_t)(b * CFULL + o)) * HW + po + tx * 4;
        float4 xv = *reinterpret_cast<const float4*>(&x[off]);
        float4 r;
        r.x = gelu_exact(acc[i][0] + bs) * xv.x;
        r.y = gelu_exact(acc[i][1] + bs) * xv.y;
        r.z = gelu_exact(acc[i][2] + bs) * xv.z;
        r.w = gelu_exact(acc[i][3] + bs) * xv.w;
        *reinterpret_cast<float4*>(&out[off]) = r;
    }
}

// ---------------------------------------------------------------------------
extern "C" void kernel_launch(void* const* d_in, const int* in_sizes, int n_in,
                              void* d_out, int out_size) {
    const float* x  = (const float*)d_in[0];
    const float* w1 = (const float*)d_in[1];
    const float* b1 = (const float*)d_in[2];
    const float* w2 = (const float*)d_in[3];
    const float* b2 = (const float*)d_in[4];
    const float* w3 = (const float*)d_in[5];
    const float* b3 = (const float*)d_in[6];
    const float* w4 = (const float*)d_in[7];
    const float* b4 = (const float*)d_in[8];
    const float* wa = (const float*)d_in[9];
    const float* ba = (const float*)d_in[10];
    float* out = (float*)d_out;

    pool_kernel<<<BATCH * HC * 4, 256>>>(x);
    base_kernel<<<BATCH, 512>>>(w2, b2, w3, b3, w4, b4, wa, ba);
    dwconv_kernel<<<(BATCH * HC * HW) / 256, 256>>>(x, w1, b1);
    gemm_gelu_kernel<<<dim3(HW / 64, CFULL / 64, BATCH), 256>>>(x, wa, out);
}

// round 2
// speedup vs baseline: 1.8304x; 1.8304x over previous
#include <cuda_runtime.h>
#include <math.h>
#include <stdint.h>

#define BATCH 4
#define CFULL 512
#define HC 256
#define HH 128
#define WW 128
#define HW (HH*WW)

// Scratch (device globals — allocation-free per harness rules)
__device__ float g_x1[BATCH * HC * HW];     // dwconv(a1) result, 64 MiB
__device__ float g_pool[BATCH * HC * 4];    // max-pool of x[:,256:] to 2x2, [b][cc][q]
__device__ float g_base[BATCH * 4 * CFULL]; // per-(batch,quadrant) bias: [b][q][o]

// ---------------------------------------------------------------------------
// Kernel 1: adaptive max pool of channels 256..511 to 2x2 (float4 loads)
// ---------------------------------------------------------------------------
__global__ __launch_bounds__(256) void pool_kernel(const float* __restrict__ x) {
    int blk = blockIdx.x;
    int q  = blk & 3;
    int cc = (blk >> 2) & 255;
    int b  = blk >> 10;
    int qh = q >> 1, qw = q & 1;
    const float* xin = x + ((size_t)(b * CFULL + 256 + cc)) * HW + qh * 64 * WW + qw * 64;
    const float4* xin4 = reinterpret_cast<const float4*>(xin);

    float m = -INFINITY;
    // 64 rows x 16 float4 per row = 1024 float4; row stride in float4 = 32
    for (int i = threadIdx.x; i < 1024; i += 256) {
        int r = i >> 4, c4 = i & 15;
        float4 v = xin4[r * 32 + c4];
        m = fmaxf(m, fmaxf(fmaxf(v.x, v.y), fmaxf(v.z, v.w)));
    }
    __shared__ float red[256];
    red[threadIdx.x] = m;
    __syncthreads();
    for (int s = 128; s > 0; s >>= 1) {
        if (threadIdx.x < s) red[threadIdx.x] = fmaxf(red[threadIdx.x], red[threadIdx.x + s]);
        __syncthreads();
    }
    if (threadIdx.x == 0) g_pool[(b * HC + cc) * 4 + q] = red[0];
}

// ---------------------------------------------------------------------------
// Kernel 2: tiny 2x2 dwconvs (levels 2/3/4) + base[b][q][o]
// ---------------------------------------------------------------------------
__global__ __launch_bounds__(512) void base_kernel(
    const float* __restrict__ w2, const float* __restrict__ b2,
    const float* __restrict__ w3, const float* __restrict__ b3,
    const float* __restrict__ w4, const float* __restrict__ b4,
    const float* __restrict__ wa, const float* __restrict__ ba)
{
    int b = blockIdx.x;
    __shared__ float catlow[256][4];
    int t = threadIdx.x;
    if (t < 256) {
        const float* wp;
        float bias;
        if (t < 128)       { wp = w2 + t * 9;         bias = b2[t];        }
        else if (t < 192)  { wp = w3 + (t - 128) * 9; bias = b3[t - 128]; }
        else               { wp = w4 + (t - 192) * 9; bias = b4[t - 192]; }
        float i00 = g_pool[(b * HC + t) * 4 + 0];
        float i01 = g_pool[(b * HC + t) * 4 + 1];
        float i10 = g_pool[(b * HC + t) * 4 + 2];
        float i11 = g_pool[(b * HC + t) * 4 + 3];
        catlow[t][0] = i00*wp[4] + i01*wp[5] + i10*wp[7] + i11*wp[8] + bias;
        catlow[t][1] = i00*wp[3] + i01*wp[4] + i10*wp[6] + i11*wp[7] + bias;
        catlow[t][2] = i00*wp[1] + i01*wp[2] + i10*wp[4] + i11*wp[5] + bias;
        catlow[t][3] = i00*wp[0] + i01*wp[1] + i10*wp[3] + i11*wp[4] + bias;
    }
    __syncthreads();
    int o = t;
    float a0 = ba[o], a1 = a0, a2 = a0, a3 = a0;
    #pragma unroll 4
    for (int cc = 0; cc < 256; ++cc) {
        float wv = wa[o * CFULL + 256 + cc];
        a0 = fmaf(wv, catlow[cc][0], a0);
        a1 = fmaf(wv, catlow[cc][1], a1);
        a2 = fmaf(wv, catlow[cc][2], a2);
        a3 = fmaf(wv, catlow[cc][3], a3);
    }
    g_base[(b * 4 + 0) * CFULL + o] = a0;
    g_base[(b * 4 + 1) * CFULL + o] = a1;
    g_base[(b * 4 + 2) * CFULL + o] = a2;
    g_base[(b * 4 + 3) * CFULL + o] = a3;
}

// ---------------------------------------------------------------------------
// Kernel 3: dwconv3x3 on channels 0..255 -> g_x1, smem-tiled.
// block = (b, c, rowblock of 8). smem tile 10x130 with halo zero-padding.
// ---------------------------------------------------------------------------
__global__ __launch_bounds__(256) void dwconv_kernel(
    const float* __restrict__ x, const float* __restrict__ w1, const float* __restrict__ b1)
{
    int blk = blockIdx.x;
    int rb = blk & 15;
    int c  = (blk >> 4) & 255;
    int b  = blk >> 12;

    __shared__ float tile[10][130];
    const float* xin = x + ((size_t)(b * CFULL + c)) * HW;
    int row0 = rb * 8 - 1;

    for (int i = threadIdx.x; i < 1300; i += 256) {
        int r = i / 130, cc = i - r * 130;
        int gr = row0 + r, gc = cc - 1;
        float v = 0.0f;
        if (gr >= 0 && gr < HH && gc >= 0 && gc < WW) v = xin[gr * WW + gc];
        tile[r][cc] = v;
    }
    __syncthreads();

    const float* wp = w1 + c * 9;
    float w00 = wp[0], w01 = wp[1], w02 = wp[2];
    float w10 = wp[3], w11 = wp[4], w12 = wp[5];
    float w20 = wp[6], w21 = wp[7], w22 = wp[8];
    float bias = b1[c];

    int r = threadIdx.x >> 5;           // 0..7  (output row within block)
    int wb = (threadIdx.x & 31) * 4;    // output col base

    float4 o;
    float* op = &o.x;
    #pragma unroll
    for (int j = 0; j < 4; ++j) {
        int col = wb + j;  // smem col index of left neighbor = col (center = col+1)
        float acc = bias;
        acc = fmaf(w00, tile[r  ][col  ], acc);
        acc = fmaf(w01, tile[r  ][col+1], acc);
        acc = fmaf(w02, tile[r  ][col+2], acc);
        acc = fmaf(w10, tile[r+1][col  ], acc);
        acc = fmaf(w11, tile[r+1][col+1], acc);
        acc = fmaf(w12, tile[r+1][col+2], acc);
        acc = fmaf(w20, tile[r+2][col  ], acc);
        acc = fmaf(w21, tile[r+2][col+1], acc);
        acc = fmaf(w22, tile[r+2][col+2], acc);
        op[j] = acc;
    }
    size_t off = ((size_t)(b * HC + c)) * HW + (rb * 8 + r) * WW + wb;
    *reinterpret_cast<float4*>(&g_x1[off]) = o;
}

// ---------------------------------------------------------------------------
// Kernel 4: tf32 tensor-core GEMM + base + exact GELU + gate
//   out[b,o,p] = gelu( sum_k wa[o,k]*x1[b,k,p] + base[b,q,o] ) * x[b,o,p]
// Block tile: M=128 (out chans) x N=128 (pixels = one image row), BK=32.
// 8 warps: 4 along M (32 each) x 2 along N (64 each). mma.m16n8k8 tf32.
// ---------------------------------------------------------------------------
__device__ __forceinline__ float gelu_exact(float v) {
    return 0.5f * v * (1.0f + erff(v * 0.70710678118654752f));
}
__device__ __forceinline__ uint32_t f2tf32(float f) {
    uint32_t r;
    asm("cvt.rna.tf32.f32 %0, %1;" : "=r"(r) : "f"(f));
    return r;
}
__device__ __forceinline__ void mma_tf32(float (&d)[4], const uint32_t (&a)[4], const uint32_t (&bb)[2]) {
    asm volatile(
        "mma.sync.aligned.m16n8k8.row.col.f32.tf32.tf32.f32 "
        "{%0,%1,%2,%3}, {%4,%5,%6,%7}, {%8,%9}, {%0,%1,%2,%3};"
        : "+f"(d[0]), "+f"(d[1]), "+f"(d[2]), "+f"(d[3])
        : "r"(a[0]), "r"(a[1]), "r"(a[2]), "r"(a[3]), "r"(bb[0]), "r"(bb[1]));
}

#define BM 128
#define BN 128
#define BK 32

__global__ __launch_bounds__(256, 2) void gemm_gelu_kernel(
    const float* __restrict__ x, const float* __restrict__ wa, float* __restrict__ out)
{
    __shared__ uint32_t As[BM][BK + 4];   // [m][k], stride 36 (conflict-free frag loads)
    __shared__ uint32_t Bs[BK][BN + 8];   // [k][n], stride 136 (conflict-free frag loads)

    int b  = blockIdx.z;
    int bx = blockIdx.x;            // image row h; pixel offset n0 = bx*128
    int m0 = blockIdx.y * BM;
    int tid = threadIdx.x;
    int lane = tid & 31, warp = tid >> 5;
    int warpM = warp & 3;           // 0..3 -> M offset warpM*32
    int warpN = warp >> 2;          // 0..1 -> N offset warpN*64

    const float* x1b = g_x1 + (size_t)b * HC * HW;
    int n0 = bx * BN;

    float acc[2][8][4] = {};

    // gmem load indices (fixed per thread)
    int am = tid >> 1;              // 0..127
    int ak = (tid & 1) * 16;        // 0 or 16
    int bk = tid >> 3;              // 0..31
    int bn = (tid & 7) * 16;        // 0,16,..,112

    for (int k0 = 0; k0 < HC; k0 += BK) {
        // A tile: wa[m0+am][k0+ak .. +15], 4 float4 -> tf32
        {
            const float4* wrow = reinterpret_cast<const float4*>(
                wa + (size_t)(m0 + am) * CFULL + k0 + ak);
            #pragma unroll
            for (int j = 0; j < 4; ++j) {
                float4 v = wrow[j];
                uint4 u;
                u.x = f2tf32(v.x); u.y = f2tf32(v.y);
                u.z = f2tf32(v.z); u.w = f2tf32(v.w);
                *reinterpret_cast<uint4*>(&As[am][ak + j * 4]) = u;
            }
        }
        // B tile: x1[k0+bk][n0+bn .. +15]
        {
            const float4* brow = reinterpret_cast<const float4*>(
                x1b + (size_t)(k0 + bk) * HW + n0 + bn);
            #pragma unroll
            for (int j = 0; j < 4; ++j) {
                float4 v = brow[j];
                uint4 u;
                u.x = f2tf32(v.x); u.y = f2tf32(v.y);
                u.z = f2tf32(v.z); u.w = f2tf32(v.w);
                *reinterpret_cast<uint4*>(&Bs[bk][bn + j * 4]) = u;
            }
        }
        __syncthreads();

        #pragma unroll
        for (int ks = 0; ks < 4; ++ks) {
            int k = ks * 8;
            uint32_t af[2][4];
            #pragma unroll
            for (int mt = 0; mt < 2; ++mt) {
                int m = warpM * 32 + mt * 16;
                af[mt][0] = As[m + (lane >> 2)    ][k + (lane & 3)    ];
                af[mt][1] = As[m + (lane >> 2) + 8][k + (lane & 3)    ];
                af[mt][2] = As[m + (lane >> 2)    ][k + (lane & 3) + 4];
                af[mt][3] = As[m + (lane >> 2) + 8][k + (lane & 3) + 4];
            }
            #pragma unroll
            for (int nt = 0; nt < 8; ++nt) {
                int n = warpN * 64 + nt * 8 + (lane >> 2);
                uint32_t bf[2];
                bf[0] = Bs[k + (lane & 3)    ][n];
                bf[1] = Bs[k + (lane & 3) + 4][n];
                mma_tf32(acc[0][nt], af[0], bf);
                mma_tf32(acc[1][nt], af[1], bf);
            }
        }
        __syncthreads();
    }

    // Epilogue: +base, exact GELU, gate by x, store.
    // q = (h>=64)*2 + (w>=64); warpN tile spans w in [warpN*64, warpN*64+64)
    int q = ((bx >= 64) ? 2 : 0) + warpN;
    const float* basep = g_base + (b * 4 + q) * CFULL;

    #pragma unroll
    for (int mt = 0; mt < 2; ++mt) {
        int mrow0 = m0 + warpM * 32 + mt * 16 + (lane >> 2);
        int mrow1 = mrow0 + 8;
        float bs0 = basep[mrow0];
        float bs1 = basep[mrow1];
        #pragma unroll
        for (int nt = 0; nt < 8; ++nt) {
            int n = n0 + warpN * 64 + nt * 8 + (lane & 3) * 2;
            size_t off0 = ((size_t)(b * CFULL + mrow0)) * HW + n;
            size_t off1 = ((size_t)(b * CFULL + mrow1)) * HW + n;
            float2 xv0 = *reinterpret_cast<const float2*>(x + off0);
            float2 xv1 = *reinterpret_cast<const float2*>(x + off1);
            float2 r0, r1;
            r0.x = gelu_exact(acc[mt][nt][0] + bs0) * xv0.x;
            r0.y = gelu_exact(acc[mt][nt][1] + bs0) * xv0.y;
            r1.x = gelu_exact(acc[mt][nt][2] + bs1) * xv1.x;
            r1.y = gelu_exact(acc[mt][nt][3] + bs1) * xv1.y;
            *reinterpret_cast<float2*>(out + off0) = r0;
            *reinterpret_cast<float2*>(out + off1) = r1;
        }
    }
}

// ---------------------------------------------------------------------------
extern "C" void kernel_launch(void* const* d_in, const int* in_sizes, int n_in,
                              void* d_out, int out_size) {
    const float* x  = (const float*)d_in[0];
    const float* w1 = (const float*)d_in[1];
    const float* b1 = (const float*)d_in[2];
    const float* w2 = (const float*)d_in[3];
    const float* b2 = (const float*)d_in[4];
    const float* w3 = (const float*)d_in[5];
    const float* b3 = (const float*)d_in[6];
    const float* w4 = (const float*)d_in[7];
    const float* b4 = (const float*)d_in[8];
    const float* wa = (const float*)d_in[9];
    const float* ba = (const float*)d_in[10];
    float* out = (float*)d_out;

    pool_kernel<<<BATCH * HC * 4, 256>>>(x);
    base_kernel<<<BATCH, 512>>>(w2, b2, w3, b3, w4, b4, wa, ba);
    dwconv_kernel<<<BATCH * HC * 16, 256>>>(x, w1, b1);
    gemm_gelu_kernel<<<dim3(HW / BN, CFULL / BM, BATCH), 256>>>(x, wa, out);
}

// round 3
// speedup vs baseline: 2.5491x; 1.3927x over previous
#include <cuda_runtime.h>
#include <math.h>
#include <stdint.h>

#define BATCH 4
#define CFULL 512
#define HC 256
#define HH 128
#define WW 128
#define HW (HH*WW)

__device__ float g_x1[BATCH * HC * HW];     // dwconv(a1) result
__device__ float g_pool[BATCH * HC * 4];    // max-pool of x[:,256:] to 2x2
__device__ float g_base[BATCH * 4 * CFULL]; // per-(batch,quadrant) bias [b][q][o]

// ---------------------------------------------------------------------------
// Kernel 1: adaptive max pool of channels 256..511 to 2x2 (float4 loads)
// ---------------------------------------------------------------------------
__global__ __launch_bounds__(256) void pool_kernel(const float* __restrict__ x) {
    int blk = blockIdx.x;
    int q  = blk & 3;
    int cc = (blk >> 2) & 255;
    int b  = blk >> 10;
    int qh = q >> 1, qw = q & 1;
    const float* xin = x + ((size_t)(b * CFULL + 256 + cc)) * HW + qh * 64 * WW + qw * 64;
    const float4* xin4 = reinterpret_cast<const float4*>(xin);

    float m = -INFINITY;
    for (int i = threadIdx.x; i < 1024; i += 256) {
        int r = i >> 4, c4 = i & 15;
        float4 v = xin4[r * 32 + c4];
        m = fmaxf(m, fmaxf(fmaxf(v.x, v.y), fmaxf(v.z, v.w)));
    }
    __shared__ float red[256];
    red[threadIdx.x] = m;
    __syncthreads();
    for (int s = 128; s > 0; s >>= 1) {
        if (threadIdx.x < s) red[threadIdx.x] = fmaxf(red[threadIdx.x], red[threadIdx.x + s]);
        __syncthreads();
    }
    if (threadIdx.x == 0) g_pool[(b * HC + cc) * 4 + q] = red[0];
}

// ---------------------------------------------------------------------------
// Kernel 2: tiny 2x2 dwconvs + base[b][q][o]. grid = 16 (b, o-chunk of 128).
// 512 threads: 4 threads per o, each sums 64 cc, shuffle-reduce.
// ---------------------------------------------------------------------------
__global__ __launch_bounds__(512) void base_kernel(
    const float* __restrict__ w2, const float* __restrict__ b2,
    const float* __restrict__ w3, const float* __restrict__ b3,
    const float* __restrict__ w4, const float* __restrict__ b4,
    const float* __restrict__ wa, const float* __restrict__ ba)
{
    int b  = blockIdx.x >> 2;
    int oc = (blockIdx.x & 3) * 128;
    __shared__ float catlow[256][4];
    int t = threadIdx.x;
    if (t < 256) {
        const float* wp;
        float bias;
        if (t < 128)       { wp = w2 + t * 9;         bias = b2[t];        }
        else if (t < 192)  { wp = w3 + (t - 128) * 9; bias = b3[t - 128]; }
        else               { wp = w4 + (t - 192) * 9; bias = b4[t - 192]; }
        float i00 = g_pool[(b * HC + t) * 4 + 0];
        float i01 = g_pool[(b * HC + t) * 4 + 1];
        float i10 = g_pool[(b * HC + t) * 4 + 2];
        float i11 = g_pool[(b * HC + t) * 4 + 3];
        catlow[t][0] = i00*wp[4] + i01*wp[5] + i10*wp[7] + i11*wp[8] + bias;
        catlow[t][1] = i00*wp[3] + i01*wp[4] + i10*wp[6] + i11*wp[7] + bias;
        catlow[t][2] = i00*wp[1] + i01*wp[2] + i10*wp[4] + i11*wp[5] + bias;
        catlow[t][3] = i00*wp[0] + i01*wp[1] + i10*wp[3] + i11*wp[4] + bias;
    }
    __syncthreads();
    int o    = oc + (t >> 2);
    int part = t & 3;
    int cc0  = part * 64;
    float a0 = 0.f, a1 = 0.f, a2 = 0.f, a3 = 0.f;
    #pragma unroll 4
    for (int cc = cc0; cc < cc0 + 64; ++cc) {
        float wv = wa[o * CFULL + 256 + cc];
        a0 = fmaf(wv, catlow[cc][0], a0);
        a1 = fmaf(wv, catlow[cc][1], a1);
        a2 = fmaf(wv, catlow[cc][2], a2);
        a3 = fmaf(wv, catlow[cc][3], a3);
    }
    #pragma unroll
    for (int off = 1; off < 4; off <<= 1) {
        a0 += __shfl_xor_sync(0xffffffff, a0, off);
        a1 += __shfl_xor_sync(0xffffffff, a1, off);
        a2 += __shfl_xor_sync(0xffffffff, a2, off);
        a3 += __shfl_xor_sync(0xffffffff, a3, off);
    }
    if (part == 0) {
        float bav = ba[o];
        g_base[(b * 4 + 0) * CFULL + o] = a0 + bav;
        g_base[(b * 4 + 1) * CFULL + o] = a1 + bav;
        g_base[(b * 4 + 2) * CFULL + o] = a2 + bav;
        g_base[(b * 4 + 3) * CFULL + o] = a3 + bav;
    }
}

// ---------------------------------------------------------------------------
// Kernel 3: dwconv3x3 on channels 0..255 -> g_x1.
// block = (b, c, half of 64 rows). smem tile 66x136, data at cols [4..131].
// ---------------------------------------------------------------------------
__global__ __launch_bounds__(256) void dwconv_kernel(
    const float* __restrict__ x, const float* __restrict__ w1, const float* __restrict__ b1)
{
    int blk  = blockIdx.x;
    int half = blk & 1;
    int c    = (blk >> 1) & 255;
    int b    = blk >> 9;
    int r0   = half * 64;

    __shared__ float tile[66][136];
    const float* xin = x + ((size_t)(b * CFULL + c)) * HW;
    const float4* xin4 = reinterpret_cast<const float4*>(xin);

    for (int i = threadIdx.x; i < 66 * 32; i += 256) {
        int r = i >> 5, c4 = i & 31;
        int gr = r0 + r - 1;
        float4 v = make_float4(0.f, 0.f, 0.f, 0.f);
        if (gr >= 0 && gr < HH) v = xin4[gr * 32 + c4];
        *reinterpret_cast<float4*>(&tile[r][4 + c4 * 4]) = v;
    }
    if (threadIdx.x < 66) {
        tile[threadIdx.x][3]   = 0.f;
        tile[threadIdx.x][132] = 0.f;
    }
    __syncthreads();

    const float* wp = w1 + c * 9;
    float w00 = wp[0], w01 = wp[1], w02 = wp[2];
    float w10 = wp[3], w11 = wp[4], w12 = wp[5];
    float w20 = wp[6], w21 = wp[7], w22 = wp[8];
    float bias = b1[c];

    int r  = threadIdx.x >> 2;          // output row 0..63 within half
    int cb = (threadIdx.x & 3) * 32;    // 32 output cols

    float* outp = g_x1 + ((size_t)(b * HC + c)) * HW + (r0 + r) * WW;

    #pragma unroll
    for (int g = 0; g < 8; ++g) {
        int c0 = cb + g * 4;            // x col base
        float4 o = make_float4(bias, bias, bias, bias);
        #pragma unroll
        for (int rr = 0; rr < 3; ++rr) {
            float wl = (rr == 0) ? w00 : (rr == 1) ? w10 : w20;
            float wc = (rr == 0) ? w01 : (rr == 1) ? w11 : w21;
            float wr = (rr == 0) ? w02 : (rr == 1) ? w12 : w22;
            const float* row = &tile[r + rr][0];
            float4 m = *reinterpret_cast<const float4*>(&row[c0 + 4]);
            float lv = row[c0 + 3];
            float rv = row[c0 + 8];
            o.x = fmaf(wl, lv,  fmaf(wc, m.x, fmaf(wr, m.y, o.x)));
            o.y = fmaf(wl, m.x, fmaf(wc, m.y, fmaf(wr, m.z, o.y)));
            o.z = fmaf(wl, m.y, fmaf(wc, m.z, fmaf(wr, m.w, o.z)));
            o.w = fmaf(wl, m.z, fmaf(wc, m.w, fmaf(wr, rv,  o.w)));
        }
        *reinterpret_cast<float4*>(&outp[c0]) = o;
    }
}

// ---------------------------------------------------------------------------
// Kernel 4: tf32 tensor GEMM (cp.async double-buffered, no cvt) + epilogue.
// Block tile 128x128, BK=32, 8 warps (4M x 2N), mma.m16n8k8 tf32.
// ---------------------------------------------------------------------------
__device__ __forceinline__ float gelu_exact(float v) {
    return 0.5f * v * (1.0f + erff(v * 0.70710678118654752f));
}
__device__ __forceinline__ void mma_tf32(float (&d)[4], const uint32_t (&a)[4], const uint32_t (&bb)[2]) {
    asm volatile(
        "mma.sync.aligned.m16n8k8.row.col.f32.tf32.tf32.f32 "
        "{%0,%1,%2,%3}, {%4,%5,%6,%7}, {%8,%9}, {%0,%1,%2,%3};"
        : "+f"(d[0]), "+f"(d[1]), "+f"(d[2]), "+f"(d[3])
        : "r"(a[0]), "r"(a[1]), "r"(a[2]), "r"(a[3]), "r"(bb[0]), "r"(bb[1]));
}
__device__ __forceinline__ void cp_async16(uint32_t dst, const void* src) {
    asm volatile("cp.async.cg.shared.global [%0], [%1], 16;" :: "r"(dst), "l"(src));
}

#define BM 128
#define BN 128
#define BK 32
#define AS_STRIDE 36
#define BS_STRIDE 136
#define AS_ELEMS (BM * AS_STRIDE)   // 4608
#define BS_ELEMS (BK * BS_STRIDE)   // 4352
#define GEMM_SMEM_BYTES ((2 * AS_ELEMS + 2 * BS_ELEMS) * 4)  // 71680

__global__ __launch_bounds__(256, 2) void gemm_gelu_kernel(
    const float* __restrict__ x, const float* __restrict__ wa, float* __restrict__ out)
{
    extern __shared__ uint32_t smem[];
    uint32_t* As0 = smem;                      // [2][BM][AS_STRIDE]
    uint32_t* Bs0 = smem + 2 * AS_ELEMS;       // [2][BK][BS_STRIDE]

    int b  = blockIdx.z;
    int bx = blockIdx.x;            // image row h; n0 = bx*128
    int m0 = blockIdx.y * BM;
    int tid = threadIdx.x;
    int lane = tid & 31, warp = tid >> 5;
    int warpM = warp & 3;
    int warpN = warp >> 2;

    const float* x1b = g_x1 + (size_t)b * HC * HW;
    int n0 = bx * BN;

    // cp.async source/dest index precompute
    int a_row[4], a_kc[4], b_row[4], b_nc[4];
    #pragma unroll
    for (int j = 0; j < 4; ++j) {
        int idx = tid + 256 * j;
        a_row[j] = idx >> 3;  a_kc[j] = (idx & 7) * 4;    // 128 rows x 8 chunks
        b_row[j] = idx >> 5;  b_nc[j] = (idx & 31) * 4;   // 32 rows x 32 chunks
    }

    uint32_t as_base = (uint32_t)__cvta_generic_to_shared(As0);
    uint32_t bs_base = (uint32_t)__cvta_generic_to_shared(Bs0);

    auto load_stage = [&](int k0, int s) {
        #pragma unroll
        for (int j = 0; j < 4; ++j) {
            const float* src = wa + (size_t)(m0 + a_row[j]) * CFULL + k0 + a_kc[j];
            uint32_t dst = as_base + (s * AS_ELEMS + a_row[j] * AS_STRIDE + a_kc[j]) * 4;
            cp_async16(dst, src);
        }
        #pragma unroll
        for (int j = 0; j < 4; ++j) {
            const float* src = x1b + (size_t)(k0 + b_row[j]) * HW + n0 + b_nc[j];
            uint32_t dst = bs_base + (s * BS_ELEMS + b_row[j] * BS_STRIDE + b_nc[j]) * 4;
            cp_async16(dst, src);
        }
        asm volatile("cp.async.commit_group;");
    };

    float acc[2][8][4] = {};

    load_stage(0, 0);

    for (int it = 0; it < HC / BK; ++it) {
        if (it < HC / BK - 1) {
            load_stage((it + 1) * BK, (it + 1) & 1);
            asm volatile("cp.async.wait_group 1;");
        } else {
            asm volatile("cp.async.wait_group 0;");
        }
        __syncthreads();

        const uint32_t* As = As0 + (it & 1) * AS_ELEMS;
        const uint32_t* Bs = Bs0 + (it & 1) * BS_ELEMS;

        #pragma unroll
        for (int ks = 0; ks < 4; ++ks) {
            int k = ks * 8;
            uint32_t af[2][4];
            #pragma unroll
            for (int mt = 0; mt < 2; ++mt) {
                int m = warpM * 32 + mt * 16;
                const uint32_t* Ar0 = As + (m + (lane >> 2)) * AS_STRIDE + k + (lane & 3);
                const uint32_t* Ar1 = Ar0 + 8 * AS_STRIDE;
                af[mt][0] = Ar0[0];
                af[mt][1] = Ar1[0];
                af[mt][2] = Ar0[4];
                af[mt][3] = Ar1[4];
            }
            #pragma unroll
            for (int nt = 0; nt < 8; ++nt) {
                int n = warpN * 64 + nt * 8 + (lane >> 2);
                const uint32_t* Bc = Bs + (k + (lane & 3)) * BS_STRIDE + n;
                uint32_t bf[2];
                bf[0] = Bc[0];
                bf[1] = Bc[4 * BS_STRIDE];
                mma_tf32(acc[0][nt], af[0], bf);
                mma_tf32(acc[1][nt], af[1], bf);
            }
        }
        __syncthreads();
    }

    // Epilogue: +base, exact GELU, gate by x, store.
    int q = ((bx >= 64) ? 2 : 0) + warpN;
    const float* basep = g_base + (b * 4 + q) * CFULL;

    #pragma unroll
    for (int mt = 0; mt < 2; ++mt) {
        int mrow0 = m0 + warpM * 32 + mt * 16 + (lane >> 2);
        int mrow1 = mrow0 + 8;
        float bs0 = basep[mrow0];
        float bs1 = basep[mrow1];
        #pragma unroll
        for (int nt = 0; nt < 8; ++nt) {
            int n = n0 + warpN * 64 + nt * 8 + (lane & 3) * 2;
            size_t off0 = ((size_t)(b * CFULL + mrow0)) * HW + n;
            size_t off1 = ((size_t)(b * CFULL + mrow1)) * HW + n;
            float2 xv0 = *reinterpret_cast<const float2*>(x + off0);
            float2 xv1 = *reinterpret_cast<const float2*>(x + off1);
            float2 r0, r1;
            r0.x = gelu_exact(acc[mt][nt][0] + bs0) * xv0.x;
            r0.y = gelu_exact(acc[mt][nt][1] + bs0) * xv0.y;
            r1.x = gelu_exact(acc[mt][nt][2] + bs1) * xv1.x;
            r1.y = gelu_exact(acc[mt][nt][3] + bs1) * xv1.y;
            *reinterpret_cast<float2*>(out + off0) = r0;
            *reinterpret_cast<float2*>(out + off1) = r1;
        }
    }
}

// ---------------------------------------------------------------------------
extern "C" void kernel_launch(void* const* d_in, const int* in_sizes, int n_in,
                              void* d_out, int out_size) {
    const float* x  = (const float*)d_in[0];
    const float* w1 = (const float*)d_in[1];
    const float* b1 = (const float*)d_in[2];
    const float* w2 = (const float*)d_in[3];
    const float* b2 = (const float*)d_in[4];
    const float* w3 = (const float*)d_in[5];
    const float* b3 = (const float*)d_in[6];
    const float* w4 = (const float*)d_in[7];
    const float* b4 = (const float*)d_in[8];
    const float* wa = (const float*)d_in[9];
    const float* ba = (const float*)d_in[10];
    float* out = (float*)d_out;

    cudaFuncSetAttribute(gemm_gelu_kernel,
                         cudaFuncAttributeMaxDynamicSharedMemorySize, GEMM_SMEM_BYTES);

    pool_kernel<<<BATCH * HC * 4, 256>>>(x);
    base_kernel<<<16, 512>>>(w2, b2, w3, b3, w4, b4, wa, ba);
    dwconv_kernel<<<BATCH * HC * 2, 256>>>(x, w1, b1);
    gemm_gelu_kernel<<<dim3(HW / BN, CFULL / BM, BATCH), 256, GEMM_SMEM_BYTES>>>(x, wa, out);
}